// round 1
// baseline (speedup 1.0000x reference)
#include <cuda_runtime.h>
#include <math.h>

// NT-Xent loss, fused Gram + logsumexp.
// z: (16384, 128) f32, rows L2-normalized. out: scalar f32.
//
// loss_i = -sim[i, i^8192] + logsumexp_j(sim[i,j], j != i),  sim = (z z^T)*2
// Since |z_i|=1, sim <= 2, use fixed max M=2: lse_i = 2 + log(sum_{j!=i} exp(sim_ij - 2)).

#define N2 16384
#define DIM 128
#define TI 128
#define NTILES (N2 / TI)   // 128
#define POS_TILE_XOR (8192 / TI)  // 64

__device__ float g_partials[NTILES];

__global__ void __launch_bounds__(256, 1) ntxent_main_kernel(const float* __restrict__ z) {
    const int bi   = blockIdx.x;
    const int tid  = threadIdx.x;
    const int tx   = tid & 15;   // 0..15 (column group)
    const int ty   = tid >> 4;   // 0..15 (row group)
    const int lane = tid & 31;
    const int w    = tid >> 5;   // warp id 0..7

    extern __shared__ float smem[];
    float* As = smem;              // k-major: As[k*128 + r], r in row tile
    float* Bs = smem + 128 * 128;  // k-major: Bs[k*128 + c]

    // ---- Load A tile (rows bi*128..) transposed into shared (k-major) ----
    {
        const float* zA = z + (size_t)bi * TI * DIM;
        #pragma unroll
        for (int j0 = 0; j0 < TI; j0 += 32) {
            int r = j0 + lane;
            const float* rowp = zA + (size_t)r * DIM + w * 16;
            #pragma unroll
            for (int q = 0; q < 4; q++) {
                float4 v = *(const float4*)(rowp + q * 4);
                int k = w * 16 + q * 4;
                As[(k + 0) * 128 + r] = v.x;
                As[(k + 1) * 128 + r] = v.y;
                As[(k + 2) * 128 + r] = v.z;
                As[(k + 3) * 128 + r] = v.w;
            }
        }
    }

    // Per-thread row state. Row mapping: u=0..3 -> r=ty*4+u ; u=4..7 -> r=64+ty*4+(u-4)
    float rowsum[8], posv[8];
    #pragma unroll
    for (int u = 0; u < 8; u++) { rowsum[u] = 0.f; posv[u] = 0.f; }

    for (int jt = 0; jt < NTILES; jt++) {
        __syncthreads();
        // ---- Load B tile (rows jt*128..) transposed into shared ----
        {
            const float* zB = z + (size_t)jt * TI * DIM;
            #pragma unroll
            for (int j0 = 0; j0 < TI; j0 += 32) {
                int c = j0 + lane;
                const float* rowp = zB + (size_t)c * DIM + w * 16;
                #pragma unroll
                for (int q = 0; q < 4; q++) {
                    float4 v = *(const float4*)(rowp + q * 4);
                    int k = w * 16 + q * 4;
                    Bs[(k + 0) * 128 + c] = v.x;
                    Bs[(k + 1) * 128 + c] = v.y;
                    Bs[(k + 2) * 128 + c] = v.z;
                    Bs[(k + 3) * 128 + c] = v.w;
                }
            }
        }
        __syncthreads();

        // ---- 128x128x128 tile GEMM: acc[u][v] = sum_k A[r(u)][k] * B[c(v)][k] ----
        float acc[8][8];
        #pragma unroll
        for (int u = 0; u < 8; u++)
            #pragma unroll
            for (int v = 0; v < 8; v++) acc[u][v] = 0.f;

        #pragma unroll 8
        for (int k = 0; k < DIM; k++) {
            const float* ak = As + k * 128;
            const float* bk = Bs + k * 128;
            float4 a0 = *(const float4*)(ak + ty * 4);
            float4 a1 = *(const float4*)(ak + 64 + ty * 4);
            float4 b0 = *(const float4*)(bk + tx * 4);
            float4 b1 = *(const float4*)(bk + 64 + tx * 4);
            float a[8] = {a0.x, a0.y, a0.z, a0.w, a1.x, a1.y, a1.z, a1.w};
            float b[8] = {b0.x, b0.y, b0.z, b0.w, b1.x, b1.y, b1.z, b1.w};
            #pragma unroll
            for (int u = 0; u < 8; u++)
                #pragma unroll
                for (int v = 0; v < 8; v++) acc[u][v] = fmaf(a[u], b[v], acc[u][v]);
        }

        // ---- Epilogue: accumulate exp(sim - 2), handle diagonal + positive ----
        #pragma unroll
        for (int u = 0; u < 8; u++) {
            #pragma unroll
            for (int v = 0; v < 8; v++) {
                rowsum[u] += __expf(2.f * acc[u][v] - 2.f);
            }
        }

        const bool diagTile = (jt == bi);
        const bool posTile  = (jt == (bi ^ POS_TILE_XOR));
        if (diagTile | posTile) {
            #pragma unroll
            for (int u = 0; u < 8; u++) {
                int r = (u < 4) ? (ty * 4 + u) : (64 + ty * 4 + (u - 4));
                int c = r;  // pos(i) and self both land at same in-tile offset
                if (((c >> 2) & 15) == tx) {
                    int v = (c & 3) + ((c < 64) ? 0 : 4);
                    float sim = 2.f * acc[u][v];
                    if (diagTile) rowsum[u] -= __expf(sim - 2.f);  // exact cancel of self term
                    else          posv[u] = sim;
                }
            }
        }
    }

    // ---- Reduce rowsum/posv across the 16 column-group threads (width-16 xor shuffle) ----
    #pragma unroll
    for (int u = 0; u < 8; u++) {
        #pragma unroll
        for (int off = 8; off >= 1; off >>= 1) {
            rowsum[u] += __shfl_xor_sync(0xffffffffu, rowsum[u], off, 16);
            posv[u]   += __shfl_xor_sync(0xffffffffu, posv[u],   off, 16);
        }
    }

    // ---- Per-row loss, deterministic block reduction ----
    __shared__ float tysum[16];
    if (tx == 0) {
        float s = 0.f;
        #pragma unroll
        for (int u = 0; u < 8; u++) {
            float lse = 2.f + logf(rowsum[u]);
            s += (lse - posv[u]);
        }
        tysum[ty] = s;
    }
    __syncthreads();
    if (tid == 0) {
        float s = 0.f;
        #pragma unroll
        for (int i = 0; i < 16; i++) s += tysum[i];
        g_partials[bi] = s;
    }
}

__global__ void ntxent_reduce_kernel(float* __restrict__ out) {
    if (threadIdx.x == 0) {
        float s = 0.f;
        for (int i = 0; i < NTILES; i++) s += g_partials[i];
        *out = s / (float)N2;
    }
}

extern "C" void kernel_launch(void* const* d_in, const int* in_sizes, int n_in,
                              void* d_out, int out_size) {
    const float* z = (const float*)d_in[0];
    float* out = (float*)d_out;

    // 128 KB dynamic shared (As + Bs). Idempotent, not stream-ordered; capture-safe.
    cudaFuncSetAttribute(ntxent_main_kernel,
                         cudaFuncAttributeMaxDynamicSharedMemorySize, 128 * 1024);

    ntxent_main_kernel<<<NTILES, 256, 128 * 1024>>>(z);
    ntxent_reduce_kernel<<<1, 32>>>(out);
}

// round 4
// speedup vs baseline: 6.3564x; 6.3564x over previous
#include <cuda_runtime.h>
#include <cuda_bf16.h>
#include <cstdint>
#include <math.h>

// NT-Xent loss via HMMA (mma.sync bf16) + fused logsumexp epilogue.
// z: (16384,128) f32 unit rows. sim = 2*(z z^T).
// loss_i = -sim[i, i^8192] + logsumexp_{j!=i} sim[i,j]; out = mean.
// |sim|<=2 -> fixed max: lse = 2 + log(sum_{j!=i} exp(sim-2)).

#define N2 16384
#define DIM 128
#define NTILES 128
#define ROWB 272                  // padded SMEM row bytes (128 bf16 + 8 pad)
#define A_OFF 0
#define B0_OFF 34816              // 128*272
#define B1_OFF 69632
#define RBUF_OFF 104448           // 4*128 floats
#define PBUF_OFF 106496           // 128 floats
#define SMEM_BYTES 107008

__device__ __nv_bfloat16 g_zbf[N2 * DIM];   // 4 MB static scratch
__device__ float g_partials[NTILES];

__device__ __forceinline__ uint32_t smem_u32(const void* p) {
    uint32_t a;
    asm("{ .reg .u64 t; cvta.to.shared.u64 t, %1; cvt.u32.u64 %0, t; }" : "=r"(a) : "l"(p));
    return a;
}
__device__ __forceinline__ void cp16(uint32_t dst, const void* src) {
    asm volatile("cp.async.cg.shared.global [%0], [%1], 16;" :: "r"(dst), "l"(src));
}
__device__ __forceinline__ void ldm_x4(uint32_t (&r)[4], uint32_t addr) {
    asm volatile("ldmatrix.sync.aligned.m8n8.x4.shared.b16 {%0,%1,%2,%3}, [%4];"
                 : "=r"(r[0]), "=r"(r[1]), "=r"(r[2]), "=r"(r[3]) : "r"(addr));
}
__device__ __forceinline__ void mma16816(float (&c)[4], const uint32_t (&a)[4],
                                         uint32_t b0, uint32_t b1) {
    asm volatile("mma.sync.aligned.m16n8k16.row.col.f32.bf16.bf16.f32 "
                 "{%0,%1,%2,%3},{%4,%5,%6,%7},{%8,%9},{%0,%1,%2,%3};"
                 : "+f"(c[0]), "+f"(c[1]), "+f"(c[2]), "+f"(c[3])
                 : "r"(a[0]), "r"(a[1]), "r"(a[2]), "r"(a[3]), "r"(b0), "r"(b1));
}
__device__ __forceinline__ float ex2(float x) {
    float y; asm("ex2.approx.f32 %0, %1;" : "=f"(y) : "f"(x)); return y;
}

__global__ void __launch_bounds__(256) convert_kernel(const float* __restrict__ z) {
    int i = blockIdx.x * blockDim.x + threadIdx.x;   // one per 4 floats
    const float4 v = ((const float4*)z)[i];
    __nv_bfloat162 lo = __floats2bfloat162_rn(v.x, v.y);
    __nv_bfloat162 hi = __floats2bfloat162_rn(v.z, v.w);
    uint2 o;
    o.x = *(const uint32_t*)&lo;
    o.y = *(const uint32_t*)&hi;
    ((uint2*)g_zbf)[i] = o;
}

__device__ __forceinline__ void prefetch_tile(uint32_t smbase, const char* gsrc, int tid) {
    #pragma unroll
    for (int i = 0; i < 8; i++) {
        int c = tid + i * 256;                 // 2048 chunks of 16B per tile
        int r = c >> 4, kc = c & 15;
        cp16(smbase + r * ROWB + kc * 16, gsrc + r * 256 + kc * 16);
    }
}

__global__ void __launch_bounds__(256, 1) ntxent_hmma_kernel() {
    extern __shared__ char sm[];
    const uint32_t s = smem_u32(sm);
    float* Rbuf = (float*)(sm + RBUF_OFF);     // [4 warp_n][128 rows]
    float* Pbuf = (float*)(sm + PBUF_OFF);     // [128 rows]

    const int bi = blockIdx.x;
    const int tid = threadIdx.x;
    const int w = tid >> 5, l = tid & 31;
    const int wm = w >> 2, wn = w & 3;         // warp grid 2 (m) x 4 (n)

    const char* zbf = (const char*)g_zbf;      // 32768 bytes per 128-row tile

    // Prologue: A tile (fixed) + B tile 0, one cp.async group
    prefetch_tile(s + A_OFF, zbf + (size_t)bi * 32768, tid);
    prefetch_tile(s + B0_OFF, zbf, tid);
    asm volatile("cp.async.commit_group;" ::: "memory");

    // Per-lane ldmatrix offsets
    const uint32_t laneA = (uint32_t)((l & 15) * ROWB + (l >> 4) * 16);
    const uint32_t laneB = (uint32_t)(((l & 7) + ((l >> 4) << 3)) * ROWB + (((l >> 3) & 1) << 4));
    const uint32_t A_warp = s + A_OFF + (uint32_t)wm * 64 * ROWB + laneA;

    float rs[8];
    #pragma unroll
    for (int u = 0; u < 8; u++) rs[u] = 0.f;

    const float C1 = 2.885390081777927f;       // 2*log2(e)
    const int posTile = bi ^ 64;

    for (int jt = 0; jt < NTILES; jt++) {
        __syncthreads();                       // prev compute done with the buffer we refill
        if (jt + 1 < NTILES)
            prefetch_tile(s + ((jt & 1) ? B0_OFF : B1_OFF),
                          zbf + (size_t)(jt + 1) * 32768, tid);
        asm volatile("cp.async.commit_group;" ::: "memory");
        asm volatile("cp.async.wait_group 1;" ::: "memory");
        __syncthreads();                       // tile jt visible to all

        const uint32_t B_warp = s + ((jt & 1) ? B1_OFF : B0_OFF)
                                  + (uint32_t)wn * 32 * ROWB + laneB;

        float acc[4][4][4];
        #pragma unroll
        for (int mf = 0; mf < 4; mf++)
            #pragma unroll
            for (int nf = 0; nf < 4; nf++)
                #pragma unroll
                for (int q = 0; q < 4; q++) acc[mf][nf][q] = 0.f;

        #pragma unroll
        for (int ks = 0; ks < 8; ks++) {
            uint32_t a[4][4], b[2][4];
            #pragma unroll
            for (int mf = 0; mf < 4; mf++)
                ldm_x4(a[mf], A_warp + mf * (16 * ROWB) + ks * 32);
            #pragma unroll
            for (int nh = 0; nh < 2; nh++)
                ldm_x4(b[nh], B_warp + nh * (16 * ROWB) + ks * 32);
            #pragma unroll
            for (int mf = 0; mf < 4; mf++)
                #pragma unroll
                for (int nf = 0; nf < 4; nf++)
                    mma16816(acc[mf][nf], a[mf], b[nf >> 1][(nf & 1) * 2],
                             b[nf >> 1][(nf & 1) * 2 + 1]);
        }

        // Fused epilogue
        if (jt != bi && jt != posTile) {
            #pragma unroll
            for (int mf = 0; mf < 4; mf++)
                #pragma unroll
                for (int nf = 0; nf < 4; nf++)
                    #pragma unroll
                    for (int q = 0; q < 4; q++)
                        rs[mf * 2 + (q >> 1)] += ex2(fmaf(acc[mf][nf][q], C1, -C1));
        } else {
            const bool isDiag = (jt == bi);
            #pragma unroll
            for (int mf = 0; mf < 4; mf++) {
                #pragma unroll
                for (int nf = 0; nf < 4; nf++) {
                    #pragma unroll
                    for (int q = 0; q < 4; q++) {
                        float a = acc[mf][nf][q];
                        int r = wm * 64 + mf * 16 + (l >> 2) + (q >> 1) * 8;
                        int c = wn * 32 + nf * 8 + 2 * (l & 3) + (q & 1);
                        float e = ex2(fmaf(a, C1, -C1));
                        if (r == c) {
                            if (isDiag) e = 0.f;       // exclude self-similarity
                            else        Pbuf[r] = 2.f * a;  // positive logit
                        }
                        rs[mf * 2 + (q >> 1)] += e;
                    }
                }
            }
        }
    }

    // Reduce across the 4 lanes sharing a row (l&3 varies), then across warp_n via SMEM
    #pragma unroll
    for (int u = 0; u < 8; u++) {
        rs[u] += __shfl_xor_sync(0xffffffffu, rs[u], 1);
        rs[u] += __shfl_xor_sync(0xffffffffu, rs[u], 2);
    }
    __syncthreads();
    if ((l & 3) == 0) {
        #pragma unroll
        for (int mf = 0; mf < 4; mf++)
            #pragma unroll
            for (int sub = 0; sub < 2; sub++) {
                int r = wm * 64 + mf * 16 + (l >> 2) + sub * 8;
                Rbuf[wn * 128 + r] = rs[mf * 2 + sub];
            }
    }
    __syncthreads();
    if (tid < 128) {
        float tot = (Rbuf[tid] + Rbuf[128 + tid]) + (Rbuf[256 + tid] + Rbuf[384 + tid]);
        Rbuf[tid] = 2.f + logf(tot) - Pbuf[tid];
    }
    __syncthreads();
    if (tid == 0) {
        float acc = 0.f;
        #pragma unroll 8
        for (int i = 0; i < 128; i++) acc += Rbuf[i];
        g_partials[bi] = acc;
    }
}

__global__ void ntxent_reduce_kernel(float* __restrict__ out) {
    if (threadIdx.x == 0) {
        float sum = 0.f;
        for (int i = 0; i < NTILES; i++) sum += g_partials[i];
        *out = sum / (float)N2;
    }
}

extern "C" void kernel_launch(void* const* d_in, const int* in_sizes, int n_in,
                              void* d_out, int out_size) {
    const float* z = (const float*)d_in[0];
    float* out = (float*)d_out;

    cudaFuncSetAttribute(ntxent_hmma_kernel,
                         cudaFuncAttributeMaxDynamicSharedMemorySize, SMEM_BYTES);

    convert_kernel<<<(N2 * DIM / 4) / 256, 256>>>(z);
    ntxent_hmma_kernel<<<NTILES, 256, SMEM_BYTES>>>();
    ntxent_reduce_kernel<<<1, 32>>>(out);
}